// round 14
// baseline (speedup 1.0000x reference)
#include <cuda_runtime.h>
#include <math.h>
#include <stdint.h>

// Problem dims (fixed by reference)
#define BB   4
#define SS   2048
#define DD   1024
#define HH   16
#define DK   64
#define DFF  4096
#define NROW (BB*SS)          // 8192
#define LEPS 1e-6f

// ---------------- scratch (static __device__, no allocations) ----------------
__device__ float g_xn  [(size_t)NROW * DD];
__device__ float g_q   [(size_t)NROW * DD];
__device__ float g_k   [(size_t)NROW * DD];
__device__ float g_v   [(size_t)NROW * DD];
__device__ float g_attn[(size_t)NROW * DD];
__device__ float g_x1  [(size_t)NROW * DD];
__device__ float g_h   [(size_t)NROW * DFF];
// pre-laid tf32 weight fragments: wq,wk,wv,wo (1M each), w1 (4M), w2 (4M)
__device__ uint32_t g_wf[(size_t)13 * 1024 * 1024];

#define WF_Q  ((size_t)0)
#define WF_K  ((size_t)1  * 1024 * 1024)
#define WF_V  ((size_t)2  * 1024 * 1024)
#define WF_O  ((size_t)3  * 1024 * 1024)
#define WF_1  ((size_t)4  * 1024 * 1024)
#define WF_2  ((size_t)8  * 1024 * 1024)

// ---------------- helpers -----------------------------------------------------
__device__ __forceinline__ uint32_t f2tf(float f) {
    uint32_t u;
    asm("cvt.rna.tf32.f32 %0, %1;" : "=r"(u) : "f"(f));
    return u;
}

#define MMA_TF32(d, a, b)                                                     \
    asm volatile("mma.sync.aligned.m16n8k8.row.col.f32.tf32.tf32.f32 "        \
                 "{%0,%1,%2,%3},{%4,%5,%6,%7},{%8,%9},{%0,%1,%2,%3};"         \
                 : "+f"(d[0]), "+f"(d[1]), "+f"(d[2]), "+f"(d[3])             \
                 : "r"(a[0]), "r"(a[1]), "r"(a[2]), "r"(a[3]),                \
                   "r"(b[0]), "r"(b[1]))

#define LDSM_X4(r0, r1, r2, r3, addr)                                         \
    asm volatile("ldmatrix.sync.aligned.m8n8.x4.shared.b16 {%0,%1,%2,%3}, [%4];" \
                 : "=r"(r0), "=r"(r1), "=r"(r2), "=r"(r3) : "r"(addr))

#define CP_ASYNC16(dst, src)                                                  \
    asm volatile("cp.async.ca.shared.global [%0], [%1], 16;"                  \
                 :: "r"(dst), "l"(src))
#define CP_COMMIT() asm volatile("cp.async.commit_group;")
#define CP_WAIT(n)  asm volatile("cp.async.wait_group %0;" :: "n"(n))

// ---------------- weight fragment pre-layout (fused launches) ------------------
__device__ __forceinline__
void wlayout_one(const float* __restrict__ W, uint32_t* __restrict__ Wf,
                 int M, int mb, int kb0)
{
    int tid = threadIdx.x;                 // 64 threads
    int lane = tid & 31, reg = tid >> 5;
    int t = lane & 3, g = lane >> 2;
    #pragma unroll
    for (int i = 0; i < 4; i++) {
        int kb = kb0 + i;
        float v = W[(size_t)(kb * 8 + t + reg * 4) * M + mb * 8 + g];
        Wf[(((size_t)kb * (M >> 3)) + mb) * 64 + lane * 2 + reg] = f2tf(v);
    }
}

__global__ void wlayout4_kernel(const float* __restrict__ wq,
                                const float* __restrict__ wk,
                                const float* __restrict__ wv,
                                const float* __restrict__ wo,
                                uint32_t* __restrict__ wf)
{
    const float* W; size_t off;
    if (blockIdx.z == 0)      { W = wq; off = WF_Q; }
    else if (blockIdx.z == 1) { W = wk; off = WF_K; }
    else if (blockIdx.z == 2) { W = wv; off = WF_V; }
    else                      { W = wo; off = WF_O; }
    wlayout_one(W, wf + off, DD, blockIdx.x, blockIdx.y * 4);
}

__global__ void wlayoutff_kernel(const float* __restrict__ w1,
                                 const float* __restrict__ w2,
                                 uint32_t* __restrict__ wf)
{
    if (blockIdx.z == 0) {
        if (blockIdx.y < DD / 32)
            wlayout_one(w1, wf + WF_1, DFF, blockIdx.x, blockIdx.y * 4);
    } else {
        if (blockIdx.x < DD / 8)
            wlayout_one(w2, wf + WF_2, DD, blockIdx.x, blockIdx.y * 4);
    }
}

// ---------------- LayerNorm (R10 block-per-row version) ------------------------
__global__ void ln_kernel(const float* __restrict__ x,
                          const float* __restrict__ w,
                          const float* __restrict__ b,
                          float* __restrict__ y)
{
    int row = blockIdx.x;
    const float* xr = x + (size_t)row * DD;
    int c = threadIdx.x * 4;
    float4 v = *(const float4*)(xr + c);
    float s  = v.x + v.y + v.z + v.w;
    float sq = v.x*v.x + v.y*v.y + v.z*v.z + v.w*v.w;
    #pragma unroll
    for (int o = 16; o; o >>= 1) {
        s  += __shfl_xor_sync(0xffffffffu, s,  o);
        sq += __shfl_xor_sync(0xffffffffu, sq, o);
    }
    __shared__ float ssm[8], sqm[8];
    int wid = threadIdx.x >> 5, lid = threadIdx.x & 31;
    if (lid == 0) { ssm[wid] = s; sqm[wid] = sq; }
    __syncthreads();
    if (wid == 0) {
        float a = (lid < 8) ? ssm[lid] : 0.f;
        float q = (lid < 8) ? sqm[lid] : 0.f;
        #pragma unroll
        for (int o = 16; o; o >>= 1) {
            a += __shfl_xor_sync(0xffffffffu, a, o);
            q += __shfl_xor_sync(0xffffffffu, q, o);
        }
        if (lid == 0) { ssm[0] = a; sqm[0] = q; }
    }
    __syncthreads();
    float sum = ssm[0], sumsq = sqm[0];
    float mean = sum * (1.0f / DD);
    float var  = (sumsq - sum * mean) * (1.0f / (DD - 1));
    float inv  = 1.0f / (sqrtf(var) + LEPS);

    float4 wv = *(const float4*)(w + c);
    float4 bv = *(const float4*)(b + c);
    float4 out;
    out.x = wv.x * (v.x - mean) * inv + bv.x;
    out.y = wv.y * (v.y - mean) * inv + bv.y;
    out.z = wv.z * (v.z - mean) * inv + bv.z;
    out.w = wv.w * (v.w - mean) * inv + bv.w;
    *(float4*)(y + (size_t)row * DD + c) = out;
}

// ---------------- TF32 GEMM: 256x128 CTA tile, warp tile 64x64 -----------------
// C[N,M] = A[N,K] @ W[K,M] + bias (+relu / +resid)
// BK=16, 4-stage cp.async ring. 8 warps: 4(m) x 2(n).
// A row-major pad-20 (ldmatrix conflict-free), B pre-laid fragments.
#define STAGES    4
#define AS_WORDS  (256 * 20)                  // 5120
#define BS_WORDS  2048
#define STG_WORDS (AS_WORDS + BS_WORDS)       // 7168
#define GSMEM_BYTES (STAGES * STG_WORDS * 4)  // 114688

template<int MODE>
__device__ __forceinline__
void tgemm_body(const float* __restrict__ A, const uint32_t* __restrict__ Wf,
                const float* __restrict__ bias, const float* __restrict__ resid,
                float* __restrict__ C, int K, int M, int bx, int by)
{
    extern __shared__ __align__(16) uint32_t dsm[];

    int tid  = threadIdx.x;
    int lane = tid & 31, warp = tid >> 5;
    int wm = warp >> 1, wn = warp & 1;        // 4 x 2 warp grid
    int g = lane >> 2, t = lane & 3;
    int row0 = by * 256, col0 = bx * 128;
    const int MB = M >> 3;
    const int KT = K >> 4;

    // A staging: each thread owns one full row (16 floats = 4 cp.async)
    int ar = tid;
    const float* Aptr = A + (size_t)(row0 + ar) * K;

    // B staging: contiguous copy of 2048 words, 8 per thread
    int bks = tid >> 7;
    int bidx = (tid & 127) * 8;
    const uint32_t* Wfp = Wf + ((size_t)bks * MB + (col0 >> 3)) * 64 + bidx;
    const size_t wstep = (size_t)2 * MB * 64;

    uint32_t smem_u32 = (uint32_t)__cvta_generic_to_shared(dsm);
    uint32_t a_dst = smem_u32 + (uint32_t)(ar * 20) * 4;
    uint32_t b_dst = smem_u32 + (uint32_t)(AS_WORDS + bks * 1024 + bidx) * 4;

    // ldmatrix address pieces
    int lm_tile = lane >> 3, lm_r = lane & 7;
    int lm_row_base = wm * 64 + (lm_tile & 1) * 8 + lm_r;
    int lm_colw = (lm_tile >> 1) * 4;

    float acc[4][8][4];
    #pragma unroll
    for (int i = 0; i < 4; i++)
        #pragma unroll
        for (int j = 0; j < 8; j++)
            #pragma unroll
            for (int r = 0; r < 4; r++) acc[i][j][r] = 0.f;

    #pragma unroll
    for (int s = 0; s < STAGES - 1; s++) {
        uint32_t soff = (uint32_t)(s * STG_WORDS) * 4;
        const float* asrc = Aptr + s * 16;
        CP_ASYNC16(a_dst + soff,      asrc);
        CP_ASYNC16(a_dst + soff + 16, asrc + 4);
        CP_ASYNC16(a_dst + soff + 32, asrc + 8);
        CP_ASYNC16(a_dst + soff + 48, asrc + 12);
        const uint32_t* bsrc = Wfp + (size_t)s * wstep;
        CP_ASYNC16(b_dst + soff,      bsrc);
        CP_ASYNC16(b_dst + soff + 16, bsrc + 4);
        CP_COMMIT();
    }

    for (int kt = 0; kt < KT; kt++) {
        CP_WAIT(STAGES - 2);
        __syncthreads();

        int pf = kt + STAGES - 1;
        if (pf < KT) {
            uint32_t soff = (uint32_t)((pf & (STAGES - 1)) * STG_WORDS) * 4;
            const float* asrc = Aptr + pf * 16;
            CP_ASYNC16(a_dst + soff,      asrc);
            CP_ASYNC16(a_dst + soff + 16, asrc + 4);
            CP_ASYNC16(a_dst + soff + 32, asrc + 8);
            CP_ASYNC16(a_dst + soff + 48, asrc + 12);
            const uint32_t* bsrc = Wfp + (size_t)pf * wstep;
            CP_ASYNC16(b_dst + soff,      bsrc);
            CP_ASYNC16(b_dst + soff + 16, bsrc + 4);
        }
        CP_COMMIT();

        int cs = kt & (STAGES - 1);
        uint32_t as_base = smem_u32 + (uint32_t)(cs * STG_WORDS) * 4;
        const uint32_t* BfS = dsm + cs * STG_WORDS + AS_WORDS;

        #pragma unroll
        for (int ks = 0; ks < 2; ks++) {
            uint32_t afr[4][4];
            #pragma unroll
            for (int im = 0; im < 4; im++) {
                int row = lm_row_base + im * 16;
                uint32_t addr = as_base + (uint32_t)(row * 20 + ks * 8 + lm_colw) * 4u;
                LDSM_X4(afr[im][0], afr[im][1], afr[im][2], afr[im][3], addr);
            }
            #pragma unroll
            for (int jn = 0; jn < 8; jn++) {
                uint32_t bfr[2];
                *(uint2*)&bfr[0] =
                    *(const uint2*)&BfS[ks * 1024 + (wn * 8 + jn) * 64 + lane * 2];
                #pragma unroll
                for (int im = 0; im < 4; im++)
                    MMA_TF32(acc[im][jn], afr[im], bfr);
            }
        }
    }

    // epilogue (fragment: c0,c1 = row g cols 2t,2t+1; c2,c3 = row g+8)
    #pragma unroll
    for (int im = 0; im < 4; im++) {
        int rA = row0 + wm * 64 + im * 16 + g;
        int rB = rA + 8;
        #pragma unroll
        for (int jn = 0; jn < 8; jn++) {
            int col = col0 + wn * 64 + jn * 8 + 2 * t;
            float bx0 = bias[col], bx1 = bias[col + 1];
            float v0 = acc[im][jn][0] + bx0;
            float v1 = acc[im][jn][1] + bx1;
            float v2 = acc[im][jn][2] + bx0;
            float v3 = acc[im][jn][3] + bx1;
            if (MODE == 1) {
                v0 = fmaxf(v0, 0.f); v1 = fmaxf(v1, 0.f);
                v2 = fmaxf(v2, 0.f); v3 = fmaxf(v3, 0.f);
            }
            size_t oA = (size_t)rA * M + col;
            size_t oB = (size_t)rB * M + col;
            if (MODE == 2) {
                float2 r0 = *(const float2*)(resid + oA);
                float2 r1 = *(const float2*)(resid + oB);
                v0 += r0.x; v1 += r0.y; v2 += r1.x; v3 += r1.y;
            }
            *(float2*)(C + oA) = make_float2(v0, v1);
            *(float2*)(C + oB) = make_float2(v2, v3);
        }
    }
}

template<int MODE>
__global__ __launch_bounds__(256, 1)
void tgemm_kernel(const float* __restrict__ A, const uint32_t* __restrict__ Wf,
                  const float* __restrict__ bias, const float* __restrict__ resid,
                  float* __restrict__ C, int K, int M)
{
    tgemm_body<MODE>(A, Wf, bias, resid, C, K, M, blockIdx.x, blockIdx.y);
}

__global__ __launch_bounds__(256, 1)
void qkv_kernel(const float* __restrict__ A, const uint32_t* __restrict__ wf,
                const float* __restrict__ bq, const float* __restrict__ bk,
                const float* __restrict__ bv,
                float* __restrict__ q, float* __restrict__ k, float* __restrict__ v)
{
    const uint32_t* W; const float* bias; float* C;
    if (blockIdx.z == 0)      { W = wf + WF_Q; bias = bq; C = q; }
    else if (blockIdx.z == 1) { W = wf + WF_K; bias = bk; C = k; }
    else                      { W = wf + WF_V; bias = bv; C = v; }
    tgemm_body<0>(A, W, bias, nullptr, C, DD, DD, blockIdx.x, blockIdx.y);
}

// ---------------- Flash attention v3 (unchanged R10) ---------------------------
#define FL_QS 0            // Q: 64 x 68
#define FL_KS 4352         // K: 64 x 68
#define FL_VS 8704         // V: 64 x 72
#define FL_MS 13312        // mask[64]
#define FL_TOT 13376       // *4 = 53504 bytes

__global__ __launch_bounds__(128)
void flash_kernel(const float* __restrict__ Q, const float* __restrict__ Kk,
                  const float* __restrict__ V, const int* __restrict__ mask,
                  float* __restrict__ O)
{
    extern __shared__ __align__(16) uint32_t smu[];
    float* Vs = (float*)(smu + FL_VS);
    int*   ms = (int*)  (smu + FL_MS);

    int tid  = threadIdx.x;
    int lane = tid & 31, wm = tid >> 5;
    int g = lane >> 2, t = lane & 3;

    int q0 = blockIdx.x * 64;
    int h  = blockIdx.y;
    int b  = blockIdx.z;

    const float* Qb = Q  + ((size_t)(b * SS + q0)) * DD + h * DK;
    const float* Kb = Kk + ((size_t)b * SS) * DD + h * DK;
    const float* Vb = V  + ((size_t)b * SS) * DD + h * DK;
    const int*   mb = mask + b * SS;

    uint32_t smem_b = (uint32_t)__cvta_generic_to_shared(smu);
    uint32_t qs_b = smem_b + FL_QS * 4;
    uint32_t ks_b = smem_b + FL_KS * 4;
    uint32_t vs_b = smem_b + FL_VS * 4;

    #pragma unroll
    for (int i = 0; i < 8; i++) {
        int c = tid + i * 128;
        int row = c >> 4, seg = c & 15;
        CP_ASYNC16(qs_b + (uint32_t)(row * 68 + seg * 4) * 4,
                   Qb + (size_t)row * DD + seg * 4);
    }
    CP_COMMIT();

    int lm_tile = lane >> 3, lm_r = lane & 7;
    int lm_half = (lm_tile & 1) * 8;
    int lm_colw = (lm_tile >> 1) * 4;
    int q_row = wm * 16 + lm_half + lm_r;

    int srcA = g * 4 + (t >> 1);
    int srcB = srcA + 2;
    int podd = t & 1;

    float acc_o[8][4];
    #pragma unroll
    for (int j = 0; j < 8; j++)
        #pragma unroll
        for (int r = 0; r < 4; r++) acc_o[j][r] = 0.f;
    float m0 = -INFINITY, m1 = -INFINITY, l0 = 0.f, l1 = 0.f;

    for (int kt = 0; kt < SS / 64; kt++) {
        int k0 = kt * 64;
        __syncthreads();

        #pragma unroll
        for (int i = 0; i < 8; i++) {
            int c = tid + i * 128;
            int row = c >> 4, seg = c & 15;
            CP_ASYNC16(ks_b + (uint32_t)(row * 68 + seg * 4) * 4,
                       Kb + (size_t)(k0 + row) * DD + seg * 4);
            CP_ASYNC16(vs_b + (uint32_t)(row * 72 + seg * 4) * 4,
                       Vb + (size_t)(k0 + row) * DD + seg * 4);
        }
        CP_COMMIT();
        if (tid < 64) ms[tid] = mb[k0 + tid];
        CP_WAIT(0);
        __syncthreads();

        float sacc[8][4];
        #pragma unroll
        for (int j = 0; j < 8; j++)
            #pragma unroll
            for (int r = 0; r < 4; r++) sacc[j][r] = 0.f;
        #pragma unroll
        for (int ks = 0; ks < 8; ks++) {
            uint32_t qa[4];
            {
                uint32_t addr = qs_b + (uint32_t)(q_row * 68 + ks * 8 + lm_colw) * 4u;
                LDSM_X4(qa[0], qa[1], qa[2], qa[3], addr);
            }
            #pragma unroll
            for (int kb = 0; kb < 4; kb++) {
                uint32_t kfr[4];
                int krow = kb * 16 + lm_half + lm_r;
                uint32_t addr = ks_b + (uint32_t)(krow * 68 + ks * 8 + lm_colw) * 4u;
                LDSM_X4(kfr[0], kfr[1], kfr[2], kfr[3], addr);
                uint32_t b0[2] = {kfr[0], kfr[2]};
                uint32_t b1[2] = {kfr[1], kfr[3]};
                MMA_TF32(sacc[kb * 2],     qa, b0);
                MMA_TF32(sacc[kb * 2 + 1], qa, b1);
            }
        }

        #pragma unroll
        for (int jn = 0; jn < 8; jn++) {
            int col = jn * 8 + 2 * t;
            bool z0 = (ms[col] == 0), z1 = (ms[col + 1] == 0);
            sacc[jn][0] = z0 ? -INFINITY : sacc[jn][0] * 0.125f;
            sacc[jn][1] = z1 ? -INFINITY : sacc[jn][1] * 0.125f;
            sacc[jn][2] = z0 ? -INFINITY : sacc[jn][2] * 0.125f;
            sacc[jn][3] = z1 ? -INFINITY : sacc[jn][3] * 0.125f;
        }

        float mx0 = -INFINITY, mx1 = -INFINITY;
        #pragma unroll
        for (int jn = 0; jn < 8; jn++) {
            mx0 = fmaxf(mx0, fmaxf(sacc[jn][0], sacc[jn][1]));
            mx1 = fmaxf(mx1, fmaxf(sacc[jn][2], sacc[jn][3]));
        }
        mx0 = fmaxf(mx0, __shfl_xor_sync(0xffffffffu, mx0, 1));
        mx0 = fmaxf(mx0, __shfl_xor_sync(0xffffffffu, mx0, 2));
        mx1 = fmaxf(mx1, __shfl_xor_sync(0xffffffffu, mx1, 1));
        mx1 = fmaxf(mx1, __shfl_xor_sync(0xffffffffu, mx1, 2));

        float mn0 = fmaxf(m0, mx0), mn1 = fmaxf(m1, mx1);
        float sc0 = (m0 == -INFINITY) ? 0.f : __expf(m0 - mn0);
        float sc1 = (m1 == -INFINITY) ? 0.f : __expf(m1 - mn1);
        float sum0 = 0.f, sum1 = 0.f;
        #pragma unroll
        for (int jn = 0; jn < 8; jn++) {
            float p0 = __expf(sacc[jn][0] - mn0);
            float p1 = __expf(sacc[jn][1] - mn0);
            float p2 = __expf(sacc[jn][2] - mn1);
            float p3 = __expf(sacc[jn][3] - mn1);
            sacc[jn][0] = p0; sacc[jn][1] = p1;
            sacc[jn][2] = p2; sacc[jn][3] = p3;
            sum0 += p0 + p1; sum1 += p2 + p3;
        }
        sum0 += __shfl_xor_sync(0xffffffffu, sum0, 1);
        sum0 += __shfl_xor_sync(0xffffffffu, sum0, 2);
        sum1 += __shfl_xor_sync(0xffffffffu, sum1, 1);
        sum1 += __shfl_xor_sync(0xffffffffu, sum1, 2);
        l0 = l0 * sc0 + sum0;  m0 = mn0;
        l1 = l1 * sc1 + sum1;  m1 = mn1;

        #pragma unroll
        for (int jn = 0; jn < 8; jn++) {
            acc_o[jn][0] *= sc0; acc_o[jn][1] *= sc0;
            acc_o[jn][2] *= sc1; acc_o[jn][3] *= sc1;
        }

        #pragma unroll
        for (int ks = 0; ks < 8; ks++) {
            float c0 = sacc[ks][0], c1 = sacc[ks][1];
            float c2 = sacc[ks][2], c3 = sacc[ks][3];
            float x0 = __shfl_sync(0xffffffffu, c0, srcA);
            float x1 = __shfl_sync(0xffffffffu, c1, srcA);
            float y0 = __shfl_sync(0xffffffffu, c0, srcB);
            float y1 = __shfl_sync(0xffffffffu, c1, srcB);
            float x2 = __shfl_sync(0xffffffffu, c2, srcA);
            float x3 = __shfl_sync(0xffffffffu, c3, srcA);
            float y2 = __shfl_sync(0xffffffffu, c2, srcB);
            float y3 = __shfl_sync(0xffffffffu, c3, srcB);
            uint32_t pa[4];
            pa[0] = __float_as_uint(podd ? x1 : x0);
            pa[1] = __float_as_uint(podd ? x3 : x2);
            pa[2] = __float_as_uint(podd ? y1 : y0);
            pa[3] = __float_as_uint(podd ? y3 : y2);

            int vr0 = (ks * 8 + t) * 72, vr1 = (ks * 8 + t + 4) * 72;
            #pragma unroll
            for (int jn = 0; jn < 8; jn++) {
                int col = jn * 8 + g;
                uint32_t vb[2];
                vb[0] = __float_as_uint(Vs[vr0 + col]);
                vb[1] = __float_as_uint(Vs[vr1 + col]);
                MMA_TF32(acc_o[jn], pa, vb);
            }
        }
    }

    float il0 = 1.0f / l0, il1 = 1.0f / l1;
    float* Ob = O + ((size_t)(b * SS + q0)) * DD + h * DK;
    int r0 = wm * 16 + g, r1 = r0 + 8;
    #pragma unroll
    for (int jn = 0; jn < 8; jn++) {
        int col = jn * 8 + 2 * t;
        *(float2*)(Ob + (size_t)r0 * DD + col) =
            make_float2(acc_o[jn][0] * il0, acc_o[jn][1] * il0);
        *(float2*)(Ob + (size_t)r1 * DD + col) =
            make_float2(acc_o[jn][2] * il1, acc_o[jn][3] * il1);
    }
}

// ---------------- launch ------------------------------------------------------
extern "C" void kernel_launch(void* const* d_in, const int* in_sizes, int n_in,
                              void* d_out, int out_size)
{
    const float* x    = (const float*)d_in[0];
    const int*   mask = (const int*)  d_in[1];
    const float* wq   = (const float*)d_in[2];
    const float* bq   = (const float*)d_in[3];
    const float* wk   = (const float*)d_in[4];
    const float* bk   = (const float*)d_in[5];
    const float* wv   = (const float*)d_in[6];
    const float* bv   = (const float*)d_in[7];
    const float* wo   = (const float*)d_in[8];
    const float* bo   = (const float*)d_in[9];
    const float* w1   = (const float*)d_in[10];
    const float* b1   = (const float*)d_in[11];
    const float* w2   = (const float*)d_in[12];
    const float* b2   = (const float*)d_in[13];
    const float* ln1w = (const float*)d_in[14];
    const float* ln1b = (const float*)d_in[15];
    const float* ln2w = (const float*)d_in[16];
    const float* ln2b = (const float*)d_in[17];
    float* out = (float*)d_out;

    float *xn, *q, *k, *v, *attn, *x1, *hb;
    uint32_t* wf;
    cudaGetSymbolAddress((void**)&xn,   g_xn);
    cudaGetSymbolAddress((void**)&q,    g_q);
    cudaGetSymbolAddress((void**)&k,    g_k);
    cudaGetSymbolAddress((void**)&v,    g_v);
    cudaGetSymbolAddress((void**)&attn, g_attn);
    cudaGetSymbolAddress((void**)&x1,   g_x1);
    cudaGetSymbolAddress((void**)&hb,   g_h);
    cudaGetSymbolAddress((void**)&wf,   g_wf);

    cudaFuncSetAttribute(flash_kernel,
                         cudaFuncAttributeMaxDynamicSharedMemorySize,
                         FL_TOT * (int)sizeof(uint32_t));
    cudaFuncSetAttribute(tgemm_kernel<1>,
                         cudaFuncAttributeMaxDynamicSharedMemorySize, GSMEM_BYTES);
    cudaFuncSetAttribute(tgemm_kernel<2>,
                         cudaFuncAttributeMaxDynamicSharedMemorySize, GSMEM_BYTES);
    cudaFuncSetAttribute(qkv_kernel,
                         cudaFuncAttributeMaxDynamicSharedMemorySize, GSMEM_BYTES);

    dim3 gD  (DD  / 128, NROW / 256);      // 8 x 32
    dim3 gQKV(DD  / 128, NROW / 256, 3);
    dim3 gF  (DFF / 128, NROW / 256);      // 32 x 32
    dim3 gAtt(SS / 64, HH, BB);

    // 0) weight fragment pre-layout (2 launches)
    wlayout4_kernel<<<dim3(DD / 8, DD / 32, 4), 64>>>(wq, wk, wv, wo, wf);
    wlayoutff_kernel<<<dim3(DFF / 8, DFF / 32, 2), 64>>>(w1, w2, wf);

    // 1) ln1
    ln_kernel<<<NROW, 256>>>(x, ln1w, ln1b, xn);
    // 2) fused QKV
    qkv_kernel<<<gQKV, 256, GSMEM_BYTES>>>(xn, wf, bq, bk, bv, q, k, v);
    // 3) attention
    flash_kernel<<<gAtt, 128, FL_TOT * sizeof(uint32_t)>>>(q, k, v, mask, attn);
    // 4) output projection + residual
    tgemm_kernel<2><<<gD, 256, GSMEM_BYTES>>>(attn, wf + WF_O, bo, x, x1, DD, DD);
    // 5) ln2
    ln_kernel<<<NROW, 256>>>(x1, ln2w, ln2b, xn);
    // 6) FFN up + relu
    tgemm_kernel<1><<<gF, 256, GSMEM_BYTES>>>(xn, wf + WF_1, b1, nullptr, hb, DD, DFF);
    // 7) FFN down + residual -> out
    tgemm_kernel<2><<<gD, 256, GSMEM_BYTES>>>(hb, wf + WF_2, b2, x1, out, DFF, DD);
}

// round 15
// speedup vs baseline: 1.3227x; 1.3227x over previous
#include <cuda_runtime.h>
#include <math.h>
#include <stdint.h>

// Problem dims (fixed by reference)
#define BB   4
#define SS   2048
#define DD   1024
#define HH   16
#define DK   64
#define DFF  4096
#define NROW (BB*SS)          // 8192
#define LEPS 1e-6f

// ---------------- scratch (static __device__, no allocations) ----------------
__device__ float g_xn  [(size_t)NROW * DD];
__device__ float g_q   [(size_t)NROW * DD];
__device__ float g_k   [(size_t)NROW * DD];
__device__ float g_v   [(size_t)NROW * DD];
__device__ float g_attn[(size_t)NROW * DD];
__device__ float g_x1  [(size_t)NROW * DD];
__device__ float g_h   [(size_t)NROW * DFF];
// pre-laid tf32 weight fragments: wq,wk,wv,wo (1M each), w1 (4M), w2 (4M)
__device__ uint32_t g_wf[(size_t)13 * 1024 * 1024];

#define WF_Q  ((size_t)0)
#define WF_K  ((size_t)1  * 1024 * 1024)
#define WF_V  ((size_t)2  * 1024 * 1024)
#define WF_O  ((size_t)3  * 1024 * 1024)
#define WF_1  ((size_t)4  * 1024 * 1024)
#define WF_2  ((size_t)8  * 1024 * 1024)

// ---------------- helpers -----------------------------------------------------
__device__ __forceinline__ uint32_t f2tf(float f) {
    uint32_t u;
    asm("cvt.rna.tf32.f32 %0, %1;" : "=r"(u) : "f"(f));
    return u;
}

#define MMA_TF32(d, a, b)                                                     \
    asm volatile("mma.sync.aligned.m16n8k8.row.col.f32.tf32.tf32.f32 "        \
                 "{%0,%1,%2,%3},{%4,%5,%6,%7},{%8,%9},{%0,%1,%2,%3};"         \
                 : "+f"(d[0]), "+f"(d[1]), "+f"(d[2]), "+f"(d[3])             \
                 : "r"(a[0]), "r"(a[1]), "r"(a[2]), "r"(a[3]),                \
                   "r"(b[0]), "r"(b[1]))

#define LDSM_X4(r0, r1, r2, r3, addr)                                         \
    asm volatile("ldmatrix.sync.aligned.m8n8.x4.shared.b16 {%0,%1,%2,%3}, [%4];" \
                 : "=r"(r0), "=r"(r1), "=r"(r2), "=r"(r3) : "r"(addr))

#define CP_ASYNC16(dst, src)                                                  \
    asm volatile("cp.async.ca.shared.global [%0], [%1], 16;"                  \
                 :: "r"(dst), "l"(src))
#define CP_COMMIT() asm volatile("cp.async.commit_group;")
#define CP_WAIT(n)  asm volatile("cp.async.wait_group %0;" :: "n"(n))

// ---------------- weight fragment pre-layout (fused launches) ------------------
__device__ __forceinline__
void wlayout_one(const float* __restrict__ W, uint32_t* __restrict__ Wf,
                 int M, int mb, int kb0)
{
    int tid = threadIdx.x;                 // 64 threads
    int lane = tid & 31, reg = tid >> 5;
    int t = lane & 3, g = lane >> 2;
    #pragma unroll
    for (int i = 0; i < 4; i++) {
        int kb = kb0 + i;
        float v = W[(size_t)(kb * 8 + t + reg * 4) * M + mb * 8 + g];
        Wf[(((size_t)kb * (M >> 3)) + mb) * 64 + lane * 2 + reg] = f2tf(v);
    }
}

__global__ void wlayout4_kernel(const float* __restrict__ wq,
                                const float* __restrict__ wk,
                                const float* __restrict__ wv,
                                const float* __restrict__ wo,
                                uint32_t* __restrict__ wf)
{
    const float* W; size_t off;
    if (blockIdx.z == 0)      { W = wq; off = WF_Q; }
    else if (blockIdx.z == 1) { W = wk; off = WF_K; }
    else if (blockIdx.z == 2) { W = wv; off = WF_V; }
    else                      { W = wo; off = WF_O; }
    wlayout_one(W, wf + off, DD, blockIdx.x, blockIdx.y * 4);
}

__global__ void wlayoutff_kernel(const float* __restrict__ w1,
                                 const float* __restrict__ w2,
                                 uint32_t* __restrict__ wf)
{
    if (blockIdx.z == 0) {
        if (blockIdx.y < DD / 32)
            wlayout_one(w1, wf + WF_1, DFF, blockIdx.x, blockIdx.y * 4);
    } else {
        if (blockIdx.x < DD / 8)
            wlayout_one(w2, wf + WF_2, DD, blockIdx.x, blockIdx.y * 4);
    }
}

// ---------------- LayerNorm (block-per-row) ------------------------------------
__global__ void ln_kernel(const float* __restrict__ x,
                          const float* __restrict__ w,
                          const float* __restrict__ b,
                          float* __restrict__ y)
{
    int row = blockIdx.x;
    const float* xr = x + (size_t)row * DD;
    int c = threadIdx.x * 4;
    float4 v = *(const float4*)(xr + c);
    float s  = v.x + v.y + v.z + v.w;
    float sq = v.x*v.x + v.y*v.y + v.z*v.z + v.w*v.w;
    #pragma unroll
    for (int o = 16; o; o >>= 1) {
        s  += __shfl_xor_sync(0xffffffffu, s,  o);
        sq += __shfl_xor_sync(0xffffffffu, sq, o);
    }
    __shared__ float ssm[8], sqm[8];
    int wid = threadIdx.x >> 5, lid = threadIdx.x & 31;
    if (lid == 0) { ssm[wid] = s; sqm[wid] = sq; }
    __syncthreads();
    if (wid == 0) {
        float a = (lid < 8) ? ssm[lid] : 0.f;
        float q = (lid < 8) ? sqm[lid] : 0.f;
        #pragma unroll
        for (int o = 16; o; o >>= 1) {
            a += __shfl_xor_sync(0xffffffffu, a, o);
            q += __shfl_xor_sync(0xffffffffu, q, o);
        }
        if (lid == 0) { ssm[0] = a; sqm[0] = q; }
    }
    __syncthreads();
    float sum = ssm[0], sumsq = sqm[0];
    float mean = sum * (1.0f / DD);
    float var  = (sumsq - sum * mean) * (1.0f / (DD - 1));
    float inv  = 1.0f / (sqrtf(var) + LEPS);

    float4 wv = *(const float4*)(w + c);
    float4 bv = *(const float4*)(b + c);
    float4 out;
    out.x = wv.x * (v.x - mean) * inv + bv.x;
    out.y = wv.y * (v.y - mean) * inv + bv.y;
    out.z = wv.z * (v.z - mean) * inv + bv.z;
    out.w = wv.w * (v.w - mean) * inv + bv.w;
    *(float4*)(y + (size_t)row * DD + c) = out;
}

// ---------------- TF32 GEMM: A via smem/ldmatrix, B via direct gmem LDG --------
// C[N,M] = A[N,K] @ W[K,M] + bias (+relu / +resid)
// 128x128 tile, BK=16, 8 warps (2m x 4n), warp tile 64x32.
// A: 4-stage cp.async ring (pad-20, ldmatrix).  B: fragment-order gmem,
// LDG.64 x8 per thread per tile, double-buffered in registers.
#define STAGES    4
#define AS_WORDS  2560                       // 128 rows x 20 words
#define GSMEM_BYTES (STAGES * AS_WORDS * 4)  // 40960

template<int MODE>
__device__ __forceinline__
void tgemm_body(const float* __restrict__ A, const uint32_t* __restrict__ Wf,
                const float* __restrict__ bias, const float* __restrict__ resid,
                float* __restrict__ C, int K, int M, int bx, int by)
{
    extern __shared__ __align__(16) uint32_t dsm[];

    int tid  = threadIdx.x;
    int lane = tid & 31, warp = tid >> 5;
    int wm = warp >> 2, wn = warp & 3;
    int g = lane >> 2, t = lane & 3;
    int row0 = by * 128, col0 = bx * 128;
    const int MB = M >> 3;
    const int KT = K >> 4;

    // A staging
    int ar = tid >> 1, aks = tid & 1;
    const float* Aptr = A + (size_t)(row0 + ar) * K + aks * 8;
    uint32_t smem_u32 = (uint32_t)__cvta_generic_to_shared(dsm);
    uint32_t a_dst = smem_u32 + (uint32_t)(ar * 20 + aks * 8) * 4;

    // B direct-gmem fragment base for this warp/lane
    // addr(ks_glob, jn) = Wf + ((ks_glob*MB) + (col0>>3) + wn*4 + jn)*64 + lane*2
    const uint32_t* Bbase = Wf + ((size_t)(col0 >> 3) + wn * 4) * 64 + lane * 2;
    const size_t bks_stride = (size_t)MB * 64;

    // ldmatrix address pieces
    int lm_tile = lane >> 3, lm_r = lane & 7;
    int lm_row_base = wm * 64 + (lm_tile & 1) * 8 + lm_r;
    int lm_colw = (lm_tile >> 1) * 4;

    float acc[4][4][4];
    #pragma unroll
    for (int i = 0; i < 4; i++)
        #pragma unroll
        for (int j = 0; j < 4; j++)
            #pragma unroll
            for (int r = 0; r < 4; r++) acc[i][j][r] = 0.f;

    // prologue: A stages 0..2
    #pragma unroll
    for (int s = 0; s < STAGES - 1; s++) {
        uint32_t soff = (uint32_t)(s * AS_WORDS) * 4;
        const float* asrc = Aptr + s * 16;
        CP_ASYNC16(a_dst + soff,      asrc);
        CP_ASYNC16(a_dst + soff + 16, asrc + 4);
        CP_COMMIT();
    }
    // B tile 0 into bcur
    uint32_t bcur[2][4][2], bnxt[2][4][2];
    #pragma unroll
    for (int ks = 0; ks < 2; ks++)
        #pragma unroll
        for (int jn = 0; jn < 4; jn++)
            *(uint2*)&bcur[ks][jn][0] =
                *(const uint2*)(Bbase + (size_t)ks * bks_stride + (size_t)jn * 64);

    for (int kt = 0; kt < KT; kt++) {
        CP_WAIT(STAGES - 2);
        __syncthreads();

        int pf = kt + STAGES - 1;
        if (pf < KT) {
            uint32_t soff = (uint32_t)((pf & (STAGES - 1)) * AS_WORDS) * 4;
            const float* asrc = Aptr + pf * 16;
            CP_ASYNC16(a_dst + soff,      asrc);
            CP_ASYNC16(a_dst + soff + 16, asrc + 4);
        }
        CP_COMMIT();

        // prefetch next tile's B fragments (LDG, covered by the MMA block)
        if (kt + 1 < KT) {
            const uint32_t* bp = Bbase + (size_t)(2 * (kt + 1)) * bks_stride;
            #pragma unroll
            for (int ks = 0; ks < 2; ks++)
                #pragma unroll
                for (int jn = 0; jn < 4; jn++)
                    *(uint2*)&bnxt[ks][jn][0] =
                        *(const uint2*)(bp + (size_t)ks * bks_stride + (size_t)jn * 64);
        }

        int cs = kt & (STAGES - 1);
        uint32_t as_base = smem_u32 + (uint32_t)(cs * AS_WORDS) * 4;

        #pragma unroll
        for (int ks = 0; ks < 2; ks++) {
            uint32_t afr[4][4];
            #pragma unroll
            for (int im = 0; im < 4; im++) {
                int row = lm_row_base + im * 16;
                uint32_t addr = as_base + (uint32_t)(row * 20 + ks * 8 + lm_colw) * 4u;
                LDSM_X4(afr[im][0], afr[im][1], afr[im][2], afr[im][3], addr);
            }
            #pragma unroll
            for (int im = 0; im < 4; im++)
                #pragma unroll
                for (int jn = 0; jn < 4; jn++)
                    MMA_TF32(acc[im][jn], afr[im], bcur[ks][jn]);
        }

        // rotate B buffers
        #pragma unroll
        for (int ks = 0; ks < 2; ks++)
            #pragma unroll
            for (int jn = 0; jn < 4; jn++) {
                bcur[ks][jn][0] = bnxt[ks][jn][0];
                bcur[ks][jn][1] = bnxt[ks][jn][1];
            }
    }

    // epilogue (fragment: c0,c1 = row g cols 2t,2t+1; c2,c3 = row g+8)
    #pragma unroll
    for (int im = 0; im < 4; im++) {
        int rA = row0 + wm * 64 + im * 16 + g;
        int rB = rA + 8;
        #pragma unroll
        for (int jn = 0; jn < 4; jn++) {
            int col = col0 + wn * 32 + jn * 8 + 2 * t;
            float bx0 = bias[col], bx1 = bias[col + 1];
            float v0 = acc[im][jn][0] + bx0;
            float v1 = acc[im][jn][1] + bx1;
            float v2 = acc[im][jn][2] + bx0;
            float v3 = acc[im][jn][3] + bx1;
            if (MODE == 1) {
                v0 = fmaxf(v0, 0.f); v1 = fmaxf(v1, 0.f);
                v2 = fmaxf(v2, 0.f); v3 = fmaxf(v3, 0.f);
            }
            size_t oA = (size_t)rA * M + col;
            size_t oB = (size_t)rB * M + col;
            if (MODE == 2) {
                float2 r0 = *(const float2*)(resid + oA);
                float2 r1 = *(const float2*)(resid + oB);
                v0 += r0.x; v1 += r0.y; v2 += r1.x; v3 += r1.y;
            }
            *(float2*)(C + oA) = make_float2(v0, v1);
            *(float2*)(C + oB) = make_float2(v2, v3);
        }
    }
}

template<int MODE>
__global__ __launch_bounds__(256, 2)
void tgemm_kernel(const float* __restrict__ A, const uint32_t* __restrict__ Wf,
                  const float* __restrict__ bias, const float* __restrict__ resid,
                  float* __restrict__ C, int K, int M)
{
    tgemm_body<MODE>(A, Wf, bias, resid, C, K, M, blockIdx.x, blockIdx.y);
}

__global__ __launch_bounds__(256, 2)
void qkv_kernel(const float* __restrict__ A, const uint32_t* __restrict__ wf,
                const float* __restrict__ bq, const float* __restrict__ bk,
                const float* __restrict__ bv,
                float* __restrict__ q, float* __restrict__ k, float* __restrict__ v)
{
    const uint32_t* W; const float* bias; float* C;
    if (blockIdx.z == 0)      { W = wf + WF_Q; bias = bq; C = q; }
    else if (blockIdx.z == 1) { W = wf + WF_K; bias = bk; C = k; }
    else                      { W = wf + WF_V; bias = bv; C = v; }
    tgemm_body<0>(A, W, bias, nullptr, C, DD, DD, blockIdx.x, blockIdx.y);
}

// ---------------- Flash attention v3 (unchanged R10) ---------------------------
#define FL_QS 0            // Q: 64 x 68
#define FL_KS 4352         // K: 64 x 68
#define FL_VS 8704         // V: 64 x 72
#define FL_MS 13312        // mask[64]
#define FL_TOT 13376       // *4 = 53504 bytes

__global__ __launch_bounds__(128)
void flash_kernel(const float* __restrict__ Q, const float* __restrict__ Kk,
                  const float* __restrict__ V, const int* __restrict__ mask,
                  float* __restrict__ O)
{
    extern __shared__ __align__(16) uint32_t smu[];
    float* Vs = (float*)(smu + FL_VS);
    int*   ms = (int*)  (smu + FL_MS);

    int tid  = threadIdx.x;
    int lane = tid & 31, wm = tid >> 5;
    int g = lane >> 2, t = lane & 3;

    int q0 = blockIdx.x * 64;
    int h  = blockIdx.y;
    int b  = blockIdx.z;

    const float* Qb = Q  + ((size_t)(b * SS + q0)) * DD + h * DK;
    const float* Kb = Kk + ((size_t)b * SS) * DD + h * DK;
    const float* Vb = V  + ((size_t)b * SS) * DD + h * DK;
    const int*   mb = mask + b * SS;

    uint32_t smem_b = (uint32_t)__cvta_generic_to_shared(smu);
    uint32_t qs_b = smem_b + FL_QS * 4;
    uint32_t ks_b = smem_b + FL_KS * 4;
    uint32_t vs_b = smem_b + FL_VS * 4;

    #pragma unroll
    for (int i = 0; i < 8; i++) {
        int c = tid + i * 128;
        int row = c >> 4, seg = c & 15;
        CP_ASYNC16(qs_b + (uint32_t)(row * 68 + seg * 4) * 4,
                   Qb + (size_t)row * DD + seg * 4);
    }
    CP_COMMIT();

    int lm_tile = lane >> 3, lm_r = lane & 7;
    int lm_half = (lm_tile & 1) * 8;
    int lm_colw = (lm_tile >> 1) * 4;
    int q_row = wm * 16 + lm_half + lm_r;

    int srcA = g * 4 + (t >> 1);
    int srcB = srcA + 2;
    int podd = t & 1;

    float acc_o[8][4];
    #pragma unroll
    for (int j = 0; j < 8; j++)
        #pragma unroll
        for (int r = 0; r < 4; r++) acc_o[j][r] = 0.f;
    float m0 = -INFINITY, m1 = -INFINITY, l0 = 0.f, l1 = 0.f;

    for (int kt = 0; kt < SS / 64; kt++) {
        int k0 = kt * 64;
        __syncthreads();

        #pragma unroll
        for (int i = 0; i < 8; i++) {
            int c = tid + i * 128;
            int row = c >> 4, seg = c & 15;
            CP_ASYNC16(ks_b + (uint32_t)(row * 68 + seg * 4) * 4,
                       Kb + (size_t)(k0 + row) * DD + seg * 4);
            CP_ASYNC16(vs_b + (uint32_t)(row * 72 + seg * 4) * 4,
                       Vb + (size_t)(k0 + row) * DD + seg * 4);
        }
        CP_COMMIT();
        if (tid < 64) ms[tid] = mb[k0 + tid];
        CP_WAIT(0);
        __syncthreads();

        float sacc[8][4];
        #pragma unroll
        for (int j = 0; j < 8; j++)
            #pragma unroll
            for (int r = 0; r < 4; r++) sacc[j][r] = 0.f;
        #pragma unroll
        for (int ks = 0; ks < 8; ks++) {
            uint32_t qa[4];
            {
                uint32_t addr = qs_b + (uint32_t)(q_row * 68 + ks * 8 + lm_colw) * 4u;
                LDSM_X4(qa[0], qa[1], qa[2], qa[3], addr);
            }
            #pragma unroll
            for (int kb = 0; kb < 4; kb++) {
                uint32_t kfr[4];
                int krow = kb * 16 + lm_half + lm_r;
                uint32_t addr = ks_b + (uint32_t)(krow * 68 + ks * 8 + lm_colw) * 4u;
                LDSM_X4(kfr[0], kfr[1], kfr[2], kfr[3], addr);
                uint32_t b0[2] = {kfr[0], kfr[2]};
                uint32_t b1[2] = {kfr[1], kfr[3]};
                MMA_TF32(sacc[kb * 2],     qa, b0);
                MMA_TF32(sacc[kb * 2 + 1], qa, b1);
            }
        }

        #pragma unroll
        for (int jn = 0; jn < 8; jn++) {
            int col = jn * 8 + 2 * t;
            bool z0 = (ms[col] == 0), z1 = (ms[col + 1] == 0);
            sacc[jn][0] = z0 ? -INFINITY : sacc[jn][0] * 0.125f;
            sacc[jn][1] = z1 ? -INFINITY : sacc[jn][1] * 0.125f;
            sacc[jn][2] = z0 ? -INFINITY : sacc[jn][2] * 0.125f;
            sacc[jn][3] = z1 ? -INFINITY : sacc[jn][3] * 0.125f;
        }

        float mx0 = -INFINITY, mx1 = -INFINITY;
        #pragma unroll
        for (int jn = 0; jn < 8; jn++) {
            mx0 = fmaxf(mx0, fmaxf(sacc[jn][0], sacc[jn][1]));
            mx1 = fmaxf(mx1, fmaxf(sacc[jn][2], sacc[jn][3]));
        }
        mx0 = fmaxf(mx0, __shfl_xor_sync(0xffffffffu, mx0, 1));
        mx0 = fmaxf(mx0, __shfl_xor_sync(0xffffffffu, mx0, 2));
        mx1 = fmaxf(mx1, __shfl_xor_sync(0xffffffffu, mx1, 1));
        mx1 = fmaxf(mx1, __shfl_xor_sync(0xffffffffu, mx1, 2));

        float mn0 = fmaxf(m0, mx0), mn1 = fmaxf(m1, mx1);
        float sc0 = (m0 == -INFINITY) ? 0.f : __expf(m0 - mn0);
        float sc1 = (m1 == -INFINITY) ? 0.f : __expf(m1 - mn1);
        float sum0 = 0.f, sum1 = 0.f;
        #pragma unroll
        for (int jn = 0; jn < 8; jn++) {
            float p0 = __expf(sacc[jn][0] - mn0);
            float p1 = __expf(sacc[jn][1] - mn0);
            float p2 = __expf(sacc[jn][2] - mn1);
            float p3 = __expf(sacc[jn][3] - mn1);
            sacc[jn][0] = p0; sacc[jn][1] = p1;
            sacc[jn][2] = p2; sacc[jn][3] = p3;
            sum0 += p0 + p1; sum1 += p2 + p3;
        }
        sum0 += __shfl_xor_sync(0xffffffffu, sum0, 1);
        sum0 += __shfl_xor_sync(0xffffffffu, sum0, 2);
        sum1 += __shfl_xor_sync(0xffffffffu, sum1, 1);
        sum1 += __shfl_xor_sync(0xffffffffu, sum1, 2);
        l0 = l0 * sc0 + sum0;  m0 = mn0;
        l1 = l1 * sc1 + sum1;  m1 = mn1;

        #pragma unroll
        for (int jn = 0; jn < 8; jn++) {
            acc_o[jn][0] *= sc0; acc_o[jn][1] *= sc0;
            acc_o[jn][2] *= sc1; acc_o[jn][3] *= sc1;
        }

        #pragma unroll
        for (int ks = 0; ks < 8; ks++) {
            float c0 = sacc[ks][0], c1 = sacc[ks][1];
            float c2 = sacc[ks][2], c3 = sacc[ks][3];
            float x0 = __shfl_sync(0xffffffffu, c0, srcA);
            float x1 = __shfl_sync(0xffffffffu, c1, srcA);
            float y0 = __shfl_sync(0xffffffffu, c0, srcB);
            float y1 = __shfl_sync(0xffffffffu, c1, srcB);
            float x2 = __shfl_sync(0xffffffffu, c2, srcA);
            float x3 = __shfl_sync(0xffffffffu, c3, srcA);
            float y2 = __shfl_sync(0xffffffffu, c2, srcB);
            float y3 = __shfl_sync(0xffffffffu, c3, srcB);
            uint32_t pa[4];
            pa[0] = __float_as_uint(podd ? x1 : x0);
            pa[1] = __float_as_uint(podd ? x3 : x2);
            pa[2] = __float_as_uint(podd ? y1 : y0);
            pa[3] = __float_as_uint(podd ? y3 : y2);

            int vr0 = (ks * 8 + t) * 72, vr1 = (ks * 8 + t + 4) * 72;
            #pragma unroll
            for (int jn = 0; jn < 8; jn++) {
                int col = jn * 8 + g;
                uint32_t vb[2];
                vb[0] = __float_as_uint(Vs[vr0 + col]);
                vb[1] = __float_as_uint(Vs[vr1 + col]);
                MMA_TF32(acc_o[jn], pa, vb);
            }
        }
    }

    float il0 = 1.0f / l0, il1 = 1.0f / l1;
    float* Ob = O + ((size_t)(b * SS + q0)) * DD + h * DK;
    int r0 = wm * 16 + g, r1 = r0 + 8;
    #pragma unroll
    for (int jn = 0; jn < 8; jn++) {
        int col = jn * 8 + 2 * t;
        *(float2*)(Ob + (size_t)r0 * DD + col) =
            make_float2(acc_o[jn][0] * il0, acc_o[jn][1] * il0);
        *(float2*)(Ob + (size_t)r1 * DD + col) =
            make_float2(acc_o[jn][2] * il1, acc_o[jn][3] * il1);
    }
}

// ---------------- launch ------------------------------------------------------
extern "C" void kernel_launch(void* const* d_in, const int* in_sizes, int n_in,
                              void* d_out, int out_size)
{
    const float* x    = (const float*)d_in[0];
    const int*   mask = (const int*)  d_in[1];
    const float* wq   = (const float*)d_in[2];
    const float* bq   = (const float*)d_in[3];
    const float* wk   = (const float*)d_in[4];
    const float* bk   = (const float*)d_in[5];
    const float* wv   = (const float*)d_in[6];
    const float* bv   = (const float*)d_in[7];
    const float* wo   = (const float*)d_in[8];
    const float* bo   = (const float*)d_in[9];
    const float* w1   = (const float*)d_in[10];
    const float* b1   = (const float*)d_in[11];
    const float* w2   = (const float*)d_in[12];
    const float* b2   = (const float*)d_in[13];
    const float* ln1w = (const float*)d_in[14];
    const float* ln1b = (const float*)d_in[15];
    const float* ln2w = (const float*)d_in[16];
    const float* ln2b = (const float*)d_in[17];
    float* out = (float*)d_out;

    float *xn, *q, *k, *v, *attn, *x1, *hb;
    uint32_t* wf;
    cudaGetSymbolAddress((void**)&xn,   g_xn);
    cudaGetSymbolAddress((void**)&q,    g_q);
    cudaGetSymbolAddress((void**)&k,    g_k);
    cudaGetSymbolAddress((void**)&v,    g_v);
    cudaGetSymbolAddress((void**)&attn, g_attn);
    cudaGetSymbolAddress((void**)&x1,   g_x1);
    cudaGetSymbolAddress((void**)&hb,   g_h);
    cudaGetSymbolAddress((void**)&wf,   g_wf);

    cudaFuncSetAttribute(flash_kernel,
                         cudaFuncAttributeMaxDynamicSharedMemorySize,
                         FL_TOT * (int)sizeof(uint32_t));
    cudaFuncSetAttribute(tgemm_kernel<1>,
                         cudaFuncAttributeMaxDynamicSharedMemorySize, GSMEM_BYTES);
    cudaFuncSetAttribute(tgemm_kernel<2>,
                         cudaFuncAttributeMaxDynamicSharedMemorySize, GSMEM_BYTES);
    cudaFuncSetAttribute(qkv_kernel,
                         cudaFuncAttributeMaxDynamicSharedMemorySize, GSMEM_BYTES);

    dim3 gD  (DD  / 128, NROW / 128);
    dim3 gQKV(DD  / 128, NROW / 128, 3);
    dim3 gF  (DFF / 128, NROW / 128);
    dim3 gAtt(SS / 64, HH, BB);

    // 0) weight fragment pre-layout (2 launches)
    wlayout4_kernel<<<dim3(DD / 8, DD / 32, 4), 64>>>(wq, wk, wv, wo, wf);
    wlayoutff_kernel<<<dim3(DFF / 8, DFF / 32, 2), 64>>>(w1, w2, wf);

    // 1) ln1
    ln_kernel<<<NROW, 256>>>(x, ln1w, ln1b, xn);
    // 2) fused QKV
    qkv_kernel<<<gQKV, 256, GSMEM_BYTES>>>(xn, wf, bq, bk, bv, q, k, v);
    // 3) attention
    flash_kernel<<<gAtt, 128, FL_TOT * sizeof(uint32_t)>>>(q, k, v, mask, attn);
    // 4) output projection + residual
    tgemm_kernel<2><<<gD, 256, GSMEM_BYTES>>>(attn, wf + WF_O, bo, x, x1, DD, DD);
    // 5) ln2
    ln_kernel<<<NROW, 256>>>(x1, ln2w, ln2b, xn);
    // 6) FFN up + relu
    tgemm_kernel<1><<<gF, 256, GSMEM_BYTES>>>(xn, wf + WF_1, b1, nullptr, hb, DD, DFF);
    // 7) FFN down + residual -> out
    tgemm_kernel<2><<<gD, 256, GSMEM_BYTES>>>(hb, wf + WF_2, b2, x1, out, DFF, DD);
}